// round 8
// baseline (speedup 1.0000x reference)
#include <cuda_runtime.h>
#include <math.h>

#define Nn   8
#define Cc   64
#define Hh   128
#define Ww   128
#define HW   (Hh * Ww)          // 16384
#define TOT  (Nn * Cc * HW)     // 8388608
#define CCK  8                  // ci chunk staged in smem
#define TILE 16

__device__ float  g_y[TOT];
__device__ double g_sum[Cc];
__device__ double g_sq[Cc];
__device__ float  g_a[Cc];
__device__ float  g_b[Cc];

// ---------------------------------------------------------------------------
__global__ void k0_zero() {
    int t = threadIdx.x;
    if (t < Cc) { g_sum[t] = 0.0; g_sq[t] = 0.0; }
}

// ---------------------------------------------------------------------------
// Pass 1: adder2d + residual -> g_y, per-channel sum/sumsq (double).
// 256 threads = 16x16 pixel tile, 1 pixel/thread, 64 fp32 accumulators.
//
// Core trick: both ops per |x-w| element are FFMA with an IMMEDIATE
// multiplier (SASS 0x823 imm-form, rt_SMSP=1 — 2x the issue rate of
// 3-reg FADD/FFMA):
//     d   = fmaf(x, 0.5f, nsw)          // nsw = -0.5*w  (staged in smem)
//     acc = fmaf(fabsf(d), -2.0f, acc)  // acc -= |x-w|  (bit-exact: pow2 scales)
// The non-unit immediates stop ptxas from canonicalizing back to FADD.
// ---------------------------------------------------------------------------
__global__ __launch_bounds__(256, 2)
void k1_adder(const float* __restrict__ x, const float* __restrict__ wgt) {
    __shared__ float xs[CCK][18][18];
    __shared__ __align__(16) float wt[CCK][Cc][12];  // -0.5*w, 9 used, pad 12
    __shared__ double ssum[Cc];
    __shared__ double ssq[Cc];

    const int n   = blockIdx.z;
    const int ty0 = blockIdx.y * TILE;
    const int tx0 = blockIdx.x * TILE;
    const int tid = threadIdx.x;
    const int tr  = tid >> 4;
    const int tc  = tid & 15;

    float acc[Cc];
#pragma unroll
    for (int i = 0; i < Cc; i++) acc[i] = 0.0f;

    for (int cb = 0; cb < Cc; cb += CCK) {
        __syncthreads();
        // stage x halo tile
        for (int i = tid; i < CCK * 18 * 18; i += 256) {
            int ci = i / 324, r = (i / 18) % 18, c = i % 18;
            int gh = ty0 - 1 + r, gw = tx0 - 1 + c;
            float v = 0.0f;
            if ((unsigned)gh < 128u && (unsigned)gw < 128u)
                v = x[((n * Cc + cb + ci) * Hh + gh) * Ww + gw];
            xs[ci][r][c] = v;
        }
        // stage scaled+negated weights: wt[ci][co][k] = -0.5 * w[co][cb+ci][k]
        for (int i = tid; i < CCK * Cc * 9; i += 256) {
            int ci  = i / (Cc * 9);
            int rem = i % (Cc * 9);
            int co  = rem / 9, k = rem % 9;
            wt[ci][co][k] = -0.5f * wgt[(co * Cc + cb + ci) * 9 + k];
        }
        __syncthreads();

#pragma unroll 1
        for (int ci = 0; ci < CCK; ci++) {
            float xv[9];
#pragma unroll
            for (int kh = 0; kh < 3; kh++)
#pragma unroll
                for (int kw = 0; kw < 3; kw++)
                    xv[kh * 3 + kw] = xs[ci][tr + kh][tc + kw];

#pragma unroll
            for (int co = 0; co < Cc; co++) {     // FULL unroll: acc[] in regs
                const float4* wv = reinterpret_cast<const float4*>(&wt[ci][co][0]);
                float4 wa = wv[0];                // k = 0..3
                float4 wb = wv[1];                // k = 4..7
                float  w8 = wt[ci][co][8];
                float a = acc[co];
                a = fmaf(fabsf(fmaf(xv[0], 0.5f, wa.x)), -2.0f, a);
                a = fmaf(fabsf(fmaf(xv[1], 0.5f, wa.y)), -2.0f, a);
                a = fmaf(fabsf(fmaf(xv[2], 0.5f, wa.z)), -2.0f, a);
                a = fmaf(fabsf(fmaf(xv[3], 0.5f, wa.w)), -2.0f, a);
                a = fmaf(fabsf(fmaf(xv[4], 0.5f, wb.x)), -2.0f, a);
                a = fmaf(fabsf(fmaf(xv[5], 0.5f, wb.y)), -2.0f, a);
                a = fmaf(fabsf(fmaf(xv[6], 0.5f, wb.z)), -2.0f, a);
                a = fmaf(fabsf(fmaf(xv[7], 0.5f, wb.w)), -2.0f, a);
                a = fmaf(fabsf(fmaf(xv[8], 0.5f, w8  )), -2.0f, a);
                acc[co] = a;
            }
        }
    }

    // ---- epilogue: residual, y store, per-channel stats
    __syncthreads();
    if (tid < Cc) { ssum[tid] = 0.0; ssq[tid] = 0.0; }
    __syncthreads();

    const int h    = ty0 + tr;
    const int w    = tx0 + tc;
    const int lane = tid & 31;
    const int pixb = n * Cc * HW + h * Ww + w;

#pragma unroll
    for (int co = 0; co < Cc; co++) {
        float y = acc[co] + x[pixb + co * HW];
        g_y[pixb + co * HW] = y;

        float s = y, q = y * y;
#pragma unroll
        for (int off = 16; off; off >>= 1) {
            s += __shfl_xor_sync(0xffffffffu, s, off);
            q += __shfl_xor_sync(0xffffffffu, q, off);
        }
        if (lane == 0) {
            atomicAdd(&ssum[co], (double)s);
            atomicAdd(&ssq[co],  (double)q);
        }
    }
    __syncthreads();
    if (tid < Cc) {
        atomicAdd(&g_sum[tid], ssum[tid]);
        atomicAdd(&g_sq[tid],  ssq[tid]);
    }
}

// ---------------------------------------------------------------------------
__global__ void k2_stats(const float* __restrict__ gamma,
                         const float* __restrict__ beta) {
    int c = threadIdx.x;
    if (c < Cc) {
        const double cnt = (double)(Nn * HW);
        double mean = g_sum[c] / cnt;
        double var  = g_sq[c] / cnt - mean * mean;
        float inv   = (float)(1.0 / sqrt(var + 1e-5));
        float a     = gamma[c] * inv;
        g_a[c] = a;
        g_b[c] = beta[c] - (float)mean * a;
    }
}

// ---------------------------------------------------------------------------
__global__ void k3_out(float* __restrict__ out, const float* __restrict__ alpha) {
    const float al = *alpha;
    int i4 = blockIdx.x * blockDim.x + threadIdx.x;
    if (i4 < TOT / 4) {
        int i = i4 * 4;
        int c = (i >> 14) & 63;                       // HW = 2^14
        float a = g_a[c], b = g_b[c];
        float4 yv = *reinterpret_cast<const float4*>(&g_y[i]);
        float t0 = yv.x * a + b;
        float t1 = yv.y * a + b;
        float t2 = yv.z * a + b;
        float t3 = yv.w * a + b;
        float4 ov;
        if (al == 1.0f) {
            ov = make_float4(t0, t1, t2, t3);   // sign(t)*(|t|+1e-12) == t to 1e-12
        } else {
            float r0 = powf(fabsf(t0) + 1e-12f, al);
            float r1 = powf(fabsf(t1) + 1e-12f, al);
            float r2 = powf(fabsf(t2) + 1e-12f, al);
            float r3 = powf(fabsf(t3) + 1e-12f, al);
            ov.x = (t0 > 0.0f) ? r0 : ((t0 < 0.0f) ? -r0 : 0.0f);
            ov.y = (t1 > 0.0f) ? r1 : ((t1 < 0.0f) ? -r1 : 0.0f);
            ov.z = (t2 > 0.0f) ? r2 : ((t2 < 0.0f) ? -r2 : 0.0f);
            ov.w = (t3 > 0.0f) ? r3 : ((t3 < 0.0f) ? -r3 : 0.0f);
        }
        *reinterpret_cast<float4*>(&out[i]) = ov;
    }
}

// ---------------------------------------------------------------------------
extern "C" void kernel_launch(void* const* d_in, const int* in_sizes, int n_in,
                              void* d_out, int out_size) {
    const float* x     = (const float*)d_in[0];
    const float* wgt   = (const float*)d_in[1];
    const float* gamma = (const float*)d_in[2];
    const float* beta  = (const float*)d_in[3];
    const float* alpha = (const float*)d_in[4];
    float* out = (float*)d_out;

    k0_zero<<<1, 64>>>();
    dim3 grid(Ww / TILE, Hh / TILE, Nn);   // 8 x 8 x 8
    k1_adder<<<grid, 256>>>(x, wgt);
    k2_stats<<<1, 64>>>(gamma, beta);
    k3_out<<<(TOT / 4 + 255) / 256, 256>>>(out, alpha);
}